// round 14
// baseline (speedup 1.0000x reference)
// R14: mma_kernel rebuilt — ldmatrix.x4 fragments (3 LDSM vs 20 LDS per k16)
// + double-buffered 32-code B chunks (cp.async wait_group<1> pipeline).
// Fragment mapping verified identical to R13's manual loads (same dists).
// All other kernels byte-identical to R13 (278.1us best).
#include <cuda_runtime.h>
#include <cuda_bf16.h>
#include <cuda_fp16.h>
#include <cstdint>

#define D_DIM 256
#define K_CODES 1024
#define HW 1024
#define N_ROWS 32768
#define AROW 264                   // padded bf16 row stride (528B)
#define BCHUNK 32                  // codes per B chunk
#define NCH (K_CODES / BCHUNK)     // 32 chunks

// ---- global scratch ----
__device__ __nv_bfloat16 g_zbf[N_ROWS * D_DIM];
__device__ float         g_zf [N_ROWS * D_DIM];
__device__ __nv_bfloat16 g_ebf[K_CODES * D_DIM];
__device__ float         g_e2 [K_CODES];
__device__ float         g_sz [N_ROWS];
__device__ __half        g_dh [(size_t)N_ROWS * K_CODES]; // s = e2-2dot (67MB)
__device__ unsigned      g_code[N_ROWS];

// ---- prep: exact e2 + bf16 codebook (identical since R9) ----
__global__ void vq_prep(const float* __restrict__ emb) {
    const int j = blockIdx.x;
    const int d = threadIdx.x;
    float v = emb[j * D_DIM + d];
    g_ebf[j * D_DIM + d] = __float2bfloat16(v);
    float s = __fmul_rn(v, v);
    #pragma unroll
    for (int o = 16; o > 0; o >>= 1)
        s = __fadd_rn(s, __shfl_down_sync(0xFFFFFFFFu, s, o));
    __shared__ float ws[8];
    if ((d & 31) == 0) ws[d >> 5] = s;
    __syncthreads();
    if (d == 0) {
        float t = ws[0];
        #pragma unroll
        for (int w = 1; w < 8; w++) t = __fadd_rn(t, ws[w]);
        g_e2[j] = t;
    }
}

// ---- z transpose (identical since R9) ----
__global__ void zt_kernel(const float* __restrict__ z) {
    __shared__ float ts[64][65];
    const int hw0 = blockIdx.x * 64;
    const int d0  = blockIdx.y * 64;
    const int b   = blockIdx.z;
    const int t = threadIdx.x;
    {
        const int dr = t >> 2, c4 = (t & 3) * 16;
        const float* src = z + ((size_t)b * D_DIM + d0 + dr) * HW + hw0 + c4;
        #pragma unroll
        for (int u = 0; u < 4; u++) {
            float4 v = *(const float4*)(src + u * 4);
            ts[dr][c4 + u * 4 + 0] = v.x;
            ts[dr][c4 + u * 4 + 1] = v.y;
            ts[dr][c4 + u * 4 + 2] = v.z;
            ts[dr][c4 + u * 4 + 3] = v.w;
        }
    }
    __syncthreads();
    {
        const int hwr = t >> 2, dc = (t & 3) * 16;
        const size_t n = (size_t)b * HW + hw0 + hwr;
        float* dstf = g_zf + n * D_DIM + d0 + dc;
        __nv_bfloat16* dstb = g_zbf + n * D_DIM + d0 + dc;
        #pragma unroll
        for (int u = 0; u < 4; u++) {
            float x0 = ts[dc + u * 4 + 0][hwr];
            float x1 = ts[dc + u * 4 + 1][hwr];
            float x2 = ts[dc + u * 4 + 2][hwr];
            float x3 = ts[dc + u * 4 + 3][hwr];
            float4 f4; f4.x = x0; f4.y = x1; f4.z = x2; f4.w = x3;
            *(float4*)(dstf + u * 4) = f4;
            __nv_bfloat162 p0, p1;
            p0.x = __float2bfloat16(x0); p0.y = __float2bfloat16(x1);
            p1.x = __float2bfloat16(x2); p1.y = __float2bfloat16(x3);
            *(__nv_bfloat162*)(dstb + u * 4 + 0) = p0;
            *(__nv_bfloat162*)(dstb + u * 4 + 2) = p1;
        }
    }
}

// ---- exact ||z||^2, sequential d (identical since R7) ----
__global__ void sz_kernel(const float* __restrict__ z) {
    const int nb = blockIdx.x * 128;
    const int b = nb / HW;
    const int hwb = nb % HW;
    const float* zp = z + (size_t)b * (D_DIM * HW) + hwb + threadIdx.x;
    float s = 0.f;
    for (int d = 0; d < D_DIM; d++) {
        float v = zp[(size_t)d * HW];
        s = __fadd_rn(s, __fmul_rn(v, v));
    }
    g_sz[nb + threadIdx.x] = s;
}

__device__ __forceinline__ void cp_async16(uint32_t dst, const void* src) {
    asm volatile("cp.async.cg.shared.global [%0], [%1], 16;\n" :: "r"(dst), "l"(src));
}
__device__ __forceinline__ void cp_commit() {
    asm volatile("cp.async.commit_group;\n" ::: "memory");
}
template <int N>
__device__ __forceinline__ void cp_wait() {
    asm volatile("cp.async.wait_group %0;\n" :: "n"(N) : "memory");
}

__device__ __forceinline__ void mma_bf16(float* c, uint32_t a0, uint32_t a1,
                                         uint32_t a2, uint32_t a3,
                                         uint32_t b0, uint32_t b1) {
    asm volatile(
        "mma.sync.aligned.m16n8k16.row.col.f32.bf16.bf16.f32 "
        "{%0,%1,%2,%3}, {%4,%5,%6,%7}, {%8,%9}, {%0,%1,%2,%3};\n"
        : "+f"(c[0]), "+f"(c[1]), "+f"(c[2]), "+f"(c[3])
        : "r"(a0), "r"(a1), "r"(a2), "r"(a3), "r"(b0), "r"(b1));
}

__device__ __forceinline__ void ldsm_x4(uint32_t& r0, uint32_t& r1,
                                        uint32_t& r2, uint32_t& r3,
                                        uint32_t addr) {
    asm volatile("ldmatrix.sync.aligned.m8n8.x4.shared.b16 {%0,%1,%2,%3}, [%4];"
                 : "=r"(r0), "=r"(r1), "=r"(r2), "=r"(r3) : "r"(addr));
}

// ---- pass 1: bf16 MMA (ldmatrix + double-buffered B) -> fp16 s-values ----
#define SMEM_AS 0
#define SMEM_BS (128 * AROW * 2)                         // 67584
#define BS_STRIDE (BCHUNK * AROW * 2)                    // 16896
#define SMEM_E2 (SMEM_BS + 2 * BS_STRIDE)                // 101376
#define SMEM_C_TOTAL (SMEM_E2 + BCHUNK * 4)              // 101504

__global__ void __launch_bounds__(256, 2) mma_kernel() {
    extern __shared__ char cs[];
    __nv_bfloat16* As = (__nv_bfloat16*)(cs + SMEM_AS);   // [128][264]
    float* e2s = (float*)(cs + SMEM_E2);

    const int t = threadIdx.x;
    const int w = t >> 5;
    const int l = t & 31;
    const int nbase = blockIdx.x * 128;
    const uint32_t as_s = (uint32_t)__cvta_generic_to_shared(cs + SMEM_AS);
    const uint32_t bs_s = (uint32_t)__cvta_generic_to_shared(cs + SMEM_BS);

    // group 0: A (128 rows x 512B) + B chunk 0
    #pragma unroll
    for (int i = 0; i < 16; i++) {
        int idx = t + 256 * i;
        int row = idx >> 5;
        int off = (idx & 31) * 16;
        cp_async16(as_s + row * (AROW * 2) + off,
                   (const char*)(g_zbf + (size_t)(nbase + row) * D_DIM) + off);
    }
    #pragma unroll
    for (int i = 0; i < 4; i++) {
        int idx = t + 256 * i;                 // 0..1023
        int row = idx >> 5;                    // 0..31
        int off = (idx & 31) * 16;
        cp_async16(bs_s + row * (AROW * 2) + off,
                   (const char*)(g_ebf) + row * (D_DIM * 2) + off);
    }
    cp_commit();

    // ldmatrix lane addresses (bytes, shared space)
    // A .x4: row = w*16 + (l&15), col halves = ((l>>4)&1)*8
    const uint32_t a_base = as_s + (w * 16 + (l & 15)) * (AROW * 2)
                                 + ((l >> 4) & 1) * 16;
    // B .x4 (two 8-code tiles): row = (l&7) + ((l>>4)<<3), col = ((l>>3)&1)*8
    const uint32_t b_lane_off = ((l & 7) + ((l >> 4) << 3)) * (AROW * 2)
                                 + ((l >> 3) & 1) * 16;

    const int rsub = w * 16 + (l >> 2);

    for (int c = 0; c < NCH; c++) {
        const int buf = c & 1;
        if (c + 1 < NCH) {      // prefetch next B chunk into other buffer
            const uint32_t bdst = bs_s + ((c + 1) & 1) * BS_STRIDE;
            const char* bsrc = (const char*)g_ebf
                             + (size_t)(c + 1) * BCHUNK * (D_DIM * 2);
            #pragma unroll
            for (int i = 0; i < 4; i++) {
                int idx = t + 256 * i;
                int row = idx >> 5;
                int off = (idx & 31) * 16;
                cp_async16(bdst + row * (AROW * 2) + off,
                           bsrc + row * (D_DIM * 2) + off);
            }
            cp_commit();
            cp_wait<1>();
        } else {
            cp_wait<0>();
        }
        if (t < BCHUNK) e2s[t] = g_e2[c * BCHUNK + t];
        __syncthreads();

        float acc[4][4];
        #pragma unroll
        for (int tt = 0; tt < 4; tt++)
            #pragma unroll
            for (int u = 0; u < 4; u++) acc[tt][u] = 0.f;

        const uint32_t bbase = bs_s + buf * BS_STRIDE + b_lane_off;
        #pragma unroll
        for (int k16 = 0; k16 < 16; k16++) {
            uint32_t a0, a1, a2, a3;
            ldsm_x4(a0, a1, a2, a3, a_base + k16 * 32);
            #pragma unroll
            for (int p = 0; p < 2; p++) {      // tts 2p, 2p+1 (16 codes)
                uint32_t b0, b1, b2, b3;
                ldsm_x4(b0, b1, b2, b3,
                        bbase + p * 16 * (AROW * 2) + k16 * 32);
                mma_bf16(acc[2 * p],     a0, a1, a2, a3, b0, b1);
                mma_bf16(acc[2 * p + 1], a0, a1, a2, a3, b2, b3);
            }
        }

        // s = e2 - 2*dot (sz cancels); store fp16
        {
            const size_t rA = (size_t)(nbase + rsub) * K_CODES;
            const size_t rB = rA + 8 * K_CODES;
            #pragma unroll
            for (int tt = 0; tt < 4; tt++) {
                const int nl = tt * 8 + 2 * (l & 3);
                const int n0 = c * BCHUNK + nl;
                const float e2a = e2s[nl], e2b = e2s[nl + 1];
                float sA0 = __fmaf_rn(-2.0f, acc[tt][0], e2a);
                float sA1 = __fmaf_rn(-2.0f, acc[tt][1], e2b);
                float sB0 = __fmaf_rn(-2.0f, acc[tt][2], e2a);
                float sB1 = __fmaf_rn(-2.0f, acc[tt][3], e2b);
                *(__half2*)&g_dh[rA + n0] = __floats2half2_rn(sA0, sA1);
                *(__half2*)&g_dh[rB + n0] = __floats2half2_rn(sB0, sB1);
            }
        }
        __syncthreads();   // e2s/buf reuse protection
    }
}

// ---- pass 2: tight band + warp-cooperative exact rescore (identical R13) ----
__global__ void argmin_kernel(const float* __restrict__ emb,
                              float* __restrict__ idxf) {
    __shared__ unsigned short cand[8][1024];
    __shared__ int ccnt[8];
    const int wrp = threadIdx.x >> 5;
    const int row = blockIdx.x * 8 + wrp;
    const int l = threadIdx.x & 31;
    if (l == 0) ccnt[wrp] = 0;
    __syncwarp();

    const uint4* dr4 = (const uint4*)(g_dh + (size_t)row * K_CODES);
    float sv[4][8];
    float m = 3.402823466e38f;
    #pragma unroll
    for (int i = 0; i < 4; i++) {
        uint4 vv = dr4[i * 32 + l];
        float2 f0 = __half22float2(*(__half2*)&vv.x);
        float2 f1 = __half22float2(*(__half2*)&vv.y);
        float2 f2 = __half22float2(*(__half2*)&vv.z);
        float2 f3 = __half22float2(*(__half2*)&vv.w);
        sv[i][0] = f0.x; sv[i][1] = f0.y; sv[i][2] = f1.x; sv[i][3] = f1.y;
        sv[i][4] = f2.x; sv[i][5] = f2.y; sv[i][6] = f3.x; sv[i][7] = f3.y;
        #pragma unroll
        for (int u = 0; u < 8; u++) m = fminf(m, sv[i][u]);
    }
    #pragma unroll
    for (int o = 16; o > 0; o >>= 1)
        m = fminf(m, __shfl_xor_sync(0xFFFFFFFFu, m, o));

    const float sz = g_sz[row];
    const float band = 5e-4f * sqrtf(sz) + 2e-4f;   // ~8.2e-3, rigorous
    const float th = m + band;

    #pragma unroll
    for (int i = 0; i < 4; i++) {
        #pragma unroll
        for (int u = 0; u < 8; u++) {
            if (sv[i][u] <= th) {
                int p = atomicAdd(&ccnt[wrp], 1);
                cand[wrp][p] = (unsigned short)((i * 32 + l) * 8 + u);
            }
        }
    }
    __syncwarp();
    const int cnt = ccnt[wrp];

    const float* zr = g_zf + (size_t)row * D_DIM;
    float zseg[8];
    #pragma unroll
    for (int u = 0; u < 8; u++) zseg[u] = zr[l * 8 + u];

    unsigned long long best = ~0ULL;
    for (int ci = 0; ci < cnt; ci++) {
        const int code = cand[wrp][ci];
        const float* er = emb + (size_t)code * D_DIM + l * 8;
        float part = 0.f;
        #pragma unroll
        for (int u = 0; u < 8; u++)
            part = __fmaf_rn(zseg[u], __ldg(&er[u]), part);
        #pragma unroll
        for (int o = 16; o > 0; o >>= 1)
            part = __fadd_rn(part, __shfl_xor_sync(0xFFFFFFFFu, part, o));
        float tt = __fadd_rn(sz, g_e2[code]);
        float dist = __fmaf_rn(-2.0f, part, tt);
        unsigned fb = __float_as_uint(dist);
        fb = (fb & 0x80000000u) ? ~fb : (fb | 0x80000000u);
        unsigned long long p =
            ((unsigned long long)fb << 32) | (unsigned long long)code;
        if (p < best) best = p;
    }
    if (l == 0) {
        const unsigned code = (unsigned)(best & 0xFFFFFFFFu);
        g_code[row] = code;
        idxf[row] = (float)code;
    }
}

// ---- epilogue (identical since R7) ----
__global__ void epi_kernel(const float* __restrict__ z,
                           const float* __restrict__ emb,
                           float* __restrict__ zq, float* __restrict__ loss) {
    const int nbase = blockIdx.x * 128;
    const int b = nbase / HW;
    const int hwbase = nbase % HW;
    const float* zb = z + (size_t)b * (D_DIM * HW) + hwbase;
    const int tid = threadIdx.x;
    const int r = tid & 127;
    const int half = tid >> 7;
    const int n = nbase + r;
    const unsigned code = g_code[n];
    const float* erow = emb + (size_t)code * D_DIM;
    float* zqb = zq + (size_t)b * (D_DIM * HW) + hwbase;
    float* lrow = loss + (size_t)n * D_DIM;
    #pragma unroll 4
    for (int sft = 0; sft < D_DIM / 2; sft++) {
        const int d = half * (D_DIM / 2) + sft;
        float zv = zb[(size_t)d * HW + r];
        float ev = __ldg(&erow[d]);
        zqb[(size_t)d * HW + r] = ev;
        float df = __fadd_rn(ev, -zv);
        lrow[d] = __fmul_rn(df, df);
    }
}

extern "C" void kernel_launch(void* const* d_in, const int* in_sizes, int n_in,
                              void* d_out, int out_size) {
    const float* z   = (const float*)d_in[0];   // [32,256,32,32]
    const float* emb = (const float*)d_in[1];   // [1024,256]
    float* out = (float*)d_out;

    const int n_z = in_sizes[0];                // 8388608
    const int N = n_z / D_DIM;                  // 32768

    float* zq   = out;
    float* idxf = out + n_z;
    float* loss = out + n_z + N;

    cudaFuncSetAttribute(mma_kernel,
                         cudaFuncAttributeMaxDynamicSharedMemorySize,
                         SMEM_C_TOTAL);

    vq_prep<<<K_CODES, D_DIM>>>(emb);
    zt_kernel<<<dim3(HW / 64, D_DIM / 64, 32), 256>>>(z);
    sz_kernel<<<N / 128, 128>>>(z);
    mma_kernel<<<N / 128, 256, SMEM_C_TOTAL>>>();
    argmin_kernel<<<N / 8, 256>>>(emb, idxf);
    epi_kernel<<<N / 128, 256>>>(z, emb, zq, loss);
}

// round 16
// speedup vs baseline: 1.1143x; 1.1143x over previous
// R16 resubmission: identical to R15 — previous bench was an infra failure
// (GB300 container failed twice), no measurement obtained.
// R15: (a) mma split-K accumulators — 8 indep HMMA chains/warp (latency
// cover), summed at end (band still rigorous); (b) loss fused into argmin
// (lanes already hold exact z + best code), epi slims to zq-only.
#include <cuda_runtime.h>
#include <cuda_bf16.h>
#include <cuda_fp16.h>
#include <cstdint>

#define D_DIM 256
#define K_CODES 1024
#define HW 1024
#define N_ROWS 32768
#define AROW 264                   // padded bf16 row stride (528B)
#define BCHUNK 32                  // codes per B chunk
#define NCH (K_CODES / BCHUNK)     // 32 chunks

// ---- global scratch ----
__device__ __nv_bfloat16 g_zbf[N_ROWS * D_DIM];
__device__ float         g_zf [N_ROWS * D_DIM];
__device__ __nv_bfloat16 g_ebf[K_CODES * D_DIM];
__device__ float         g_e2 [K_CODES];
__device__ float         g_sz [N_ROWS];
__device__ __half        g_dh [(size_t)N_ROWS * K_CODES]; // s = e2-2dot (67MB)
__device__ unsigned      g_code[N_ROWS];

// ---- prep: exact e2 + bf16 codebook (identical since R9) ----
__global__ void vq_prep(const float* __restrict__ emb) {
    const int j = blockIdx.x;
    const int d = threadIdx.x;
    float v = emb[j * D_DIM + d];
    g_ebf[j * D_DIM + d] = __float2bfloat16(v);
    float s = __fmul_rn(v, v);
    #pragma unroll
    for (int o = 16; o > 0; o >>= 1)
        s = __fadd_rn(s, __shfl_down_sync(0xFFFFFFFFu, s, o));
    __shared__ float ws[8];
    if ((d & 31) == 0) ws[d >> 5] = s;
    __syncthreads();
    if (d == 0) {
        float t = ws[0];
        #pragma unroll
        for (int w = 1; w < 8; w++) t = __fadd_rn(t, ws[w]);
        g_e2[j] = t;
    }
}

// ---- z transpose (identical since R9) ----
__global__ void zt_kernel(const float* __restrict__ z) {
    __shared__ float ts[64][65];
    const int hw0 = blockIdx.x * 64;
    const int d0  = blockIdx.y * 64;
    const int b   = blockIdx.z;
    const int t = threadIdx.x;
    {
        const int dr = t >> 2, c4 = (t & 3) * 16;
        const float* src = z + ((size_t)b * D_DIM + d0 + dr) * HW + hw0 + c4;
        #pragma unroll
        for (int u = 0; u < 4; u++) {
            float4 v = *(const float4*)(src + u * 4);
            ts[dr][c4 + u * 4 + 0] = v.x;
            ts[dr][c4 + u * 4 + 1] = v.y;
            ts[dr][c4 + u * 4 + 2] = v.z;
            ts[dr][c4 + u * 4 + 3] = v.w;
        }
    }
    __syncthreads();
    {
        const int hwr = t >> 2, dc = (t & 3) * 16;
        const size_t n = (size_t)b * HW + hw0 + hwr;
        float* dstf = g_zf + n * D_DIM + d0 + dc;
        __nv_bfloat16* dstb = g_zbf + n * D_DIM + d0 + dc;
        #pragma unroll
        for (int u = 0; u < 4; u++) {
            float x0 = ts[dc + u * 4 + 0][hwr];
            float x1 = ts[dc + u * 4 + 1][hwr];
            float x2 = ts[dc + u * 4 + 2][hwr];
            float x3 = ts[dc + u * 4 + 3][hwr];
            float4 f4; f4.x = x0; f4.y = x1; f4.z = x2; f4.w = x3;
            *(float4*)(dstf + u * 4) = f4;
            __nv_bfloat162 p0, p1;
            p0.x = __float2bfloat16(x0); p0.y = __float2bfloat16(x1);
            p1.x = __float2bfloat16(x2); p1.y = __float2bfloat16(x3);
            *(__nv_bfloat162*)(dstb + u * 4 + 0) = p0;
            *(__nv_bfloat162*)(dstb + u * 4 + 2) = p1;
        }
    }
}

// ---- exact ||z||^2, sequential d (identical since R7) ----
__global__ void sz_kernel(const float* __restrict__ z) {
    const int nb = blockIdx.x * 128;
    const int b = nb / HW;
    const int hwb = nb % HW;
    const float* zp = z + (size_t)b * (D_DIM * HW) + hwb + threadIdx.x;
    float s = 0.f;
    for (int d = 0; d < D_DIM; d++) {
        float v = zp[(size_t)d * HW];
        s = __fadd_rn(s, __fmul_rn(v, v));
    }
    g_sz[nb + threadIdx.x] = s;
}

__device__ __forceinline__ void cp_async16(uint32_t dst, const void* src) {
    asm volatile("cp.async.cg.shared.global [%0], [%1], 16;\n" :: "r"(dst), "l"(src));
}
__device__ __forceinline__ void cp_commit() {
    asm volatile("cp.async.commit_group;\n" ::: "memory");
}
template <int N>
__device__ __forceinline__ void cp_wait() {
    asm volatile("cp.async.wait_group %0;\n" :: "n"(N) : "memory");
}

__device__ __forceinline__ void mma_bf16(float* c, uint32_t a0, uint32_t a1,
                                         uint32_t a2, uint32_t a3,
                                         uint32_t b0, uint32_t b1) {
    asm volatile(
        "mma.sync.aligned.m16n8k16.row.col.f32.bf16.bf16.f32 "
        "{%0,%1,%2,%3}, {%4,%5,%6,%7}, {%8,%9}, {%0,%1,%2,%3};\n"
        : "+f"(c[0]), "+f"(c[1]), "+f"(c[2]), "+f"(c[3])
        : "r"(a0), "r"(a1), "r"(a2), "r"(a3), "r"(b0), "r"(b1));
}

__device__ __forceinline__ void ldsm_x4(uint32_t& r0, uint32_t& r1,
                                        uint32_t& r2, uint32_t& r3,
                                        uint32_t addr) {
    asm volatile("ldmatrix.sync.aligned.m8n8.x4.shared.b16 {%0,%1,%2,%3}, [%4];"
                 : "=r"(r0), "=r"(r1), "=r"(r2), "=r"(r3) : "r"(addr));
}

// ---- pass 1: bf16 MMA (ldmatrix, double-buffered B, split-K ILP) ----
#define SMEM_AS 0
#define SMEM_BS (128 * AROW * 2)                         // 67584
#define BS_STRIDE (BCHUNK * AROW * 2)                    // 16896
#define SMEM_E2 (SMEM_BS + 2 * BS_STRIDE)                // 101376
#define SMEM_C_TOTAL (SMEM_E2 + BCHUNK * 4)              // 101504

__global__ void __launch_bounds__(256, 2) mma_kernel() {
    extern __shared__ char cs[];
    float* e2s = (float*)(cs + SMEM_E2);

    const int t = threadIdx.x;
    const int w = t >> 5;
    const int l = t & 31;
    const int nbase = blockIdx.x * 128;
    const uint32_t as_s = (uint32_t)__cvta_generic_to_shared(cs + SMEM_AS);
    const uint32_t bs_s = (uint32_t)__cvta_generic_to_shared(cs + SMEM_BS);

    // group 0: A (128 rows x 512B) + B chunk 0
    #pragma unroll
    for (int i = 0; i < 16; i++) {
        int idx = t + 256 * i;
        int row = idx >> 5;
        int off = (idx & 31) * 16;
        cp_async16(as_s + row * (AROW * 2) + off,
                   (const char*)(g_zbf + (size_t)(nbase + row) * D_DIM) + off);
    }
    #pragma unroll
    for (int i = 0; i < 4; i++) {
        int idx = t + 256 * i;
        int row = idx >> 5;
        int off = (idx & 31) * 16;
        cp_async16(bs_s + row * (AROW * 2) + off,
                   (const char*)(g_ebf) + row * (D_DIM * 2) + off);
    }
    cp_commit();

    const uint32_t a_base = as_s + (w * 16 + (l & 15)) * (AROW * 2)
                                 + ((l >> 4) & 1) * 16;
    const uint32_t b_lane_off = ((l & 7) + ((l >> 4) << 3)) * (AROW * 2)
                                 + ((l >> 3) & 1) * 16;

    const int rsub = w * 16 + (l >> 2);

    for (int c = 0; c < NCH; c++) {
        const int buf = c & 1;
        if (c + 1 < NCH) {
            const uint32_t bdst = bs_s + ((c + 1) & 1) * BS_STRIDE;
            const char* bsrc = (const char*)g_ebf
                             + (size_t)(c + 1) * BCHUNK * (D_DIM * 2);
            #pragma unroll
            for (int i = 0; i < 4; i++) {
                int idx = t + 256 * i;
                int row = idx >> 5;
                int off = (idx & 31) * 16;
                cp_async16(bdst + row * (AROW * 2) + off,
                           bsrc + row * (D_DIM * 2) + off);
            }
            cp_commit();
            cp_wait<1>();
        } else {
            cp_wait<0>();
        }
        if (t < BCHUNK) e2s[t] = g_e2[c * BCHUNK + t];
        __syncthreads();

        // Split-K: two independent chain sets (k16 0-7, 8-15) -> 8 indep
        // HMMA chains/warp. Summed at end; error bound only shrinks.
        float accL[4][4], accR[4][4];
        #pragma unroll
        for (int tt = 0; tt < 4; tt++)
            #pragma unroll
            for (int u = 0; u < 4; u++) { accL[tt][u] = 0.f; accR[tt][u] = 0.f; }

        const uint32_t bbase = bs_s + buf * BS_STRIDE + b_lane_off;
        #pragma unroll
        for (int k16 = 0; k16 < 8; k16++) {
            uint32_t aL0, aL1, aL2, aL3, aR0, aR1, aR2, aR3;
            ldsm_x4(aL0, aL1, aL2, aL3, a_base + k16 * 32);
            ldsm_x4(aR0, aR1, aR2, aR3, a_base + (k16 + 8) * 32);
            #pragma unroll
            for (int p = 0; p < 2; p++) {
                uint32_t bL0, bL1, bL2, bL3, bR0, bR1, bR2, bR3;
                ldsm_x4(bL0, bL1, bL2, bL3,
                        bbase + p * 16 * (AROW * 2) + k16 * 32);
                ldsm_x4(bR0, bR1, bR2, bR3,
                        bbase + p * 16 * (AROW * 2) + (k16 + 8) * 32);
                mma_bf16(accL[2 * p],     aL0, aL1, aL2, aL3, bL0, bL1);
                mma_bf16(accR[2 * p],     aR0, aR1, aR2, aR3, bR0, bR1);
                mma_bf16(accL[2 * p + 1], aL0, aL1, aL2, aL3, bL2, bL3);
                mma_bf16(accR[2 * p + 1], aR0, aR1, aR2, aR3, bR2, bR3);
            }
        }

        // s = e2 - 2*(dotL + dotR); store fp16
        {
            const size_t rA = (size_t)(nbase + rsub) * K_CODES;
            const size_t rB = rA + 8 * K_CODES;
            #pragma unroll
            for (int tt = 0; tt < 4; tt++) {
                const int nl = tt * 8 + 2 * (l & 3);
                const int n0 = c * BCHUNK + nl;
                const float e2a = e2s[nl], e2b = e2s[nl + 1];
                float d0 = __fadd_rn(accL[tt][0], accR[tt][0]);
                float d1 = __fadd_rn(accL[tt][1], accR[tt][1]);
                float d2 = __fadd_rn(accL[tt][2], accR[tt][2]);
                float d3 = __fadd_rn(accL[tt][3], accR[tt][3]);
                float sA0 = __fmaf_rn(-2.0f, d0, e2a);
                float sA1 = __fmaf_rn(-2.0f, d1, e2b);
                float sB0 = __fmaf_rn(-2.0f, d2, e2a);
                float sB1 = __fmaf_rn(-2.0f, d3, e2b);
                *(__half2*)&g_dh[rA + n0] = __floats2half2_rn(sA0, sA1);
                *(__half2*)&g_dh[rB + n0] = __floats2half2_rn(sB0, sB1);
            }
        }
        __syncthreads();
    }
}

// ---- pass 2: band + exact rescore + FUSED loss write ----
__global__ void argmin_kernel(const float* __restrict__ emb,
                              float* __restrict__ idxf,
                              float* __restrict__ loss) {
    __shared__ unsigned short cand[8][1024];
    __shared__ int ccnt[8];
    const int wrp = threadIdx.x >> 5;
    const int row = blockIdx.x * 8 + wrp;
    const int l = threadIdx.x & 31;
    if (l == 0) ccnt[wrp] = 0;
    __syncwarp();

    const uint4* dr4 = (const uint4*)(g_dh + (size_t)row * K_CODES);
    float sv[4][8];
    float m = 3.402823466e38f;
    #pragma unroll
    for (int i = 0; i < 4; i++) {
        uint4 vv = dr4[i * 32 + l];
        float2 f0 = __half22float2(*(__half2*)&vv.x);
        float2 f1 = __half22float2(*(__half2*)&vv.y);
        float2 f2 = __half22float2(*(__half2*)&vv.z);
        float2 f3 = __half22float2(*(__half2*)&vv.w);
        sv[i][0] = f0.x; sv[i][1] = f0.y; sv[i][2] = f1.x; sv[i][3] = f1.y;
        sv[i][4] = f2.x; sv[i][5] = f2.y; sv[i][6] = f3.x; sv[i][7] = f3.y;
        #pragma unroll
        for (int u = 0; u < 8; u++) m = fminf(m, sv[i][u]);
    }
    #pragma unroll
    for (int o = 16; o > 0; o >>= 1)
        m = fminf(m, __shfl_xor_sync(0xFFFFFFFFu, m, o));

    const float sz = g_sz[row];
    const float band = 5e-4f * sqrtf(sz) + 2e-4f;   // ~8.2e-3, rigorous
    const float th = m + band;

    #pragma unroll
    for (int i = 0; i < 4; i++) {
        #pragma unroll
        for (int u = 0; u < 8; u++) {
            if (sv[i][u] <= th) {
                int p = atomicAdd(&ccnt[wrp], 1);
                cand[wrp][p] = (unsigned short)((i * 32 + l) * 8 + u);
            }
        }
    }
    __syncwarp();
    const int cnt = ccnt[wrp];

    const float* zr = g_zf + (size_t)row * D_DIM;
    float zseg[8];
    #pragma unroll
    for (int u = 0; u < 8; u++) zseg[u] = zr[l * 8 + u];

    unsigned long long best = ~0ULL;
    for (int ci = 0; ci < cnt; ci++) {
        const int code = cand[wrp][ci];
        const float* er = emb + (size_t)code * D_DIM + l * 8;
        float part = 0.f;
        #pragma unroll
        for (int u = 0; u < 8; u++)
            part = __fmaf_rn(zseg[u], __ldg(&er[u]), part);
        #pragma unroll
        for (int o = 16; o > 0; o >>= 1)
            part = __fadd_rn(part, __shfl_xor_sync(0xFFFFFFFFu, part, o));
        float tt = __fadd_rn(sz, g_e2[code]);
        float dist = __fmaf_rn(-2.0f, part, tt);
        unsigned fb = __float_as_uint(dist);
        fb = (fb & 0x80000000u) ? ~fb : (fb | 0x80000000u);
        unsigned long long p =
            ((unsigned long long)fb << 32) | (unsigned long long)code;
        if (p < best) best = p;
    }
    // every lane holds the identical best (dists were shfl-broadcast)
    const unsigned codeB = (unsigned)(best & 0xFFFFFFFFu);
    // fused loss: identical ops to old epi — fl(fl(e-z)^2)
    {
        const float* erB = emb + (size_t)codeB * D_DIM + l * 8;
        float* lrow = loss + (size_t)row * D_DIM + l * 8;
        #pragma unroll
        for (int u = 0; u < 8; u++) {
            float ev = __ldg(&erB[u]);
            float df = __fadd_rn(ev, -zseg[u]);
            lrow[u] = __fmul_rn(df, df);
        }
    }
    if (l == 0) {
        g_code[row] = codeB;
        idxf[row] = (float)codeB;
    }
}

// ---- epilogue: zq only (loss moved to argmin) ----
__global__ void epi_kernel(const float* __restrict__ emb,
                           float* __restrict__ zq) {
    const int nbase = blockIdx.x * 128;
    const int b = nbase / HW;
    const int hwbase = nbase % HW;
    const int tid = threadIdx.x;
    const int r = tid & 127;
    const int half = tid >> 7;
    const int n = nbase + r;
    const unsigned code = g_code[n];
    const float* erow = emb + (size_t)code * D_DIM;
    float* zqb = zq + (size_t)b * (D_DIM * HW) + hwbase;
    #pragma unroll 4
    for (int sft = 0; sft < D_DIM / 2; sft++) {
        const int d = half * (D_DIM / 2) + sft;
        zqb[(size_t)d * HW + r] = __ldg(&erow[d]);
    }
}

extern "C" void kernel_launch(void* const* d_in, const int* in_sizes, int n_in,
                              void* d_out, int out_size) {
    const float* z   = (const float*)d_in[0];   // [32,256,32,32]
    const float* emb = (const float*)d_in[1];   // [1024,256]
    float* out = (float*)d_out;

    const int n_z = in_sizes[0];                // 8388608
    const int N = n_z / D_DIM;                  // 32768

    float* zq   = out;
    float* idxf = out + n_z;
    float* loss = out + n_z + N;

    cudaFuncSetAttribute(mma_kernel,
                         cudaFuncAttributeMaxDynamicSharedMemorySize,
                         SMEM_C_TOTAL);

    vq_prep<<<K_CODES, D_DIM>>>(emb);
    zt_kernel<<<dim3(HW / 64, D_DIM / 64, 32), 256>>>(z);
    sz_kernel<<<N / 128, 128>>>(z);
    mma_kernel<<<N / 128, 256, SMEM_C_TOTAL>>>();
    argmin_kernel<<<N / 8, 256>>>(emb, idxf, loss);
    epi_kernel<<<N / 128, 256>>>(emb, zq);
}